// round 3
// baseline (speedup 1.0000x reference)
#include <cuda_runtime.h>
#include <stdint.h>

// Problem constants
#define BATCH 8
#define H 2048
#define W 2048
#define HW (H * W)
#define TOPK 8192
#define MAXP 400000      // per-batch peak capacity (expected ~167k)
#define CAP 16384        // gather/sort capacity (>= TOPK + ties)

// ---------------- device scratch (static allocation, allowed) ----------------
__device__ unsigned long long d_peaks[BATCH][MAXP];   // key = (~float_bits)<<32 | idx
__device__ int                d_pcount[BATCH];
__device__ unsigned int       d_hist[BATCH][256];
__device__ unsigned int       d_prefix[BATCH];
__device__ unsigned int       d_maskv[BATCH];
__device__ int                d_krem[BATCH];
__device__ int                d_cntge[BATCH];
__device__ unsigned long long d_sortbuf[BATCH][CAP];

// ---------------- init ----------------
__global__ void init_kernel() {
    int t = threadIdx.x;
    if (t < BATCH) {
        d_pcount[t] = 0;
        d_prefix[t] = 0u;
        d_maskv[t]  = 0u;
        d_krem[t]   = TOPK;
        d_cntge[t]  = 0;
    }
    for (int i = t; i < BATCH * 256; i += blockDim.x)
        ((unsigned int*)d_hist)[i] = 0u;
}

// ---------------- NMS: 5x5 local max, emit peaks (non-border) ----------------
#define TX 128
#define TY 16

__global__ void nms_kernel(const float* __restrict__ s) {
    __shared__ float tile[TY + 4][TX + 4];   // 20 x 132
    __shared__ float hmax[TY + 4][TX];       // 20 x 128

    int b  = blockIdx.z;
    int x0 = blockIdx.x * TX;
    int y0 = blockIdx.y * TY;
    const float* img = s + (size_t)b * HW;
    int tid = threadIdx.x;  // 256 threads

    // Load tile + halo (clamped; clamped values only influence discarded border outputs)
    for (int i = tid; i < (TY + 4) * (TX + 4); i += 256) {
        int r = i / (TX + 4), c = i % (TX + 4);
        int gy = min(max(y0 + r - 2, 0), H - 1);
        int gx = min(max(x0 + c - 2, 0), W - 1);
        tile[r][c] = img[gy * W + gx];
    }
    __syncthreads();

    // Horizontal 5-max
    for (int i = tid; i < (TY + 4) * TX; i += 256) {
        int r = i / TX, c = i % TX;
        float m = tile[r][c];
        m = fmaxf(m, tile[r][c + 1]);
        m = fmaxf(m, tile[r][c + 2]);
        m = fmaxf(m, tile[r][c + 3]);
        m = fmaxf(m, tile[r][c + 4]);
        hmax[r][c] = m;
    }
    __syncthreads();

    // Vertical 5-max + peak test (warp-aggregated atomic append)
    int c  = tid & 127;
    int r0 = tid >> 7;  // 0 or 1; uniform within a warp (warps are 32-aligned)
    for (int rr = r0; rr < TY; rr += 2) {
        float v = tile[rr + 2][c + 2];
        float m = hmax[rr][c];
        m = fmaxf(m, hmax[rr + 1][c]);
        m = fmaxf(m, hmax[rr + 2][c]);
        m = fmaxf(m, hmax[rr + 3][c]);
        m = fmaxf(m, hmax[rr + 4][c]);
        int gx = x0 + c, gy = y0 + rr;
        // v <= m always (v is inside the window); peak <=> v == window max
        bool peak = (v >= m) && (gx >= 2) && (gx < W - 2) && (gy >= 2) && (gy < H - 2);

        unsigned ball = __ballot_sync(0xffffffffu, peak);
        if (ball) {
            int lane   = tid & 31;
            int leader = __ffs(ball) - 1;
            int base   = 0;
            if (lane == leader) base = atomicAdd(&d_pcount[b], __popc(ball));
            base = __shfl_sync(0xffffffffu, base, leader);
            if (peak) {
                int off = base + __popc(ball & ((1u << lane) - 1u));
                if (off < MAXP) {
                    unsigned ub  = ~__float_as_uint(v);     // ascending ub == descending value
                    unsigned idx = (unsigned)(gy * W + gx); // flat index within batch
                    d_peaks[b][off] = ((unsigned long long)ub << 32) | idx;
                }
            }
        }
    }
}

// ---------------- radix-select (K-th smallest of ~bits), one byte per pass ----------------
__global__ void hist_kernel(int level) {
    __shared__ unsigned int sh[256];
    int b = blockIdx.y;
    int t = threadIdx.x;
    if (t < 256) sh[t] = 0u;
    __syncthreads();

    int n = min(d_pcount[b], MAXP);
    unsigned pref = d_prefix[b], msk = d_maskv[b];
    int shift = level * 8;
    for (int i = blockIdx.x * blockDim.x + t; i < n; i += gridDim.x * blockDim.x) {
        unsigned u = (unsigned)(d_peaks[b][i] >> 32);
        if ((u & msk) == pref) atomicAdd(&sh[(u >> shift) & 255u], 1u);
    }
    __syncthreads();
    if (t < 256 && sh[t]) atomicAdd(&d_hist[b][t], sh[t]);
}

__global__ void select_kernel(int level) {
    int b = threadIdx.x;
    if (b >= BATCH) return;
    unsigned krem = (unsigned)d_krem[b];
    unsigned run = 0u;
    int digit = 255;
    for (int c = 0; c < 256; c++) {
        unsigned h = d_hist[b][c];
        if (krem <= run + h) { digit = c; break; }
        run += h;
    }
    d_krem[b]    = (int)(krem - run);
    d_prefix[b] |= ((unsigned)digit) << (level * 8);
    d_maskv[b]  |= 0xFFu << (level * 8);
    for (int c = 0; c < 256; c++) d_hist[b][c] = 0u;  // reset for next pass
}

// ---------------- gather all candidates with u <= threshold ----------------
__global__ void gather_kernel() {
    int b = blockIdx.y;
    int n = min(d_pcount[b], MAXP);
    unsigned T = d_prefix[b];
    for (int i = blockIdx.x * blockDim.x + threadIdx.x; i < n; i += gridDim.x * blockDim.x) {
        unsigned long long key = d_peaks[b][i];
        unsigned u = (unsigned)(key >> 32);
        if (u <= T) {
            int pos = atomicAdd(&d_cntge[b], 1);
            if (pos < CAP) d_sortbuf[b][pos] = key;
        }
    }
}

// ---------------- per-batch bitonic sort (value desc, idx asc) ----------------
extern __shared__ unsigned long long ssort[];
__global__ void sort_kernel() {
    int b   = blockIdx.x;
    int cnt = min(d_cntge[b], CAP);
    int N   = (cnt <= 8192) ? 8192 : 16384;

    for (int i = threadIdx.x; i < N; i += blockDim.x)
        ssort[i] = (i < cnt) ? d_sortbuf[b][i] : 0xFFFFFFFFFFFFFFFFull;
    __syncthreads();

    for (int k = 2; k <= N; k <<= 1) {
        for (int j = k >> 1; j > 0; j >>= 1) {
            for (int i = threadIdx.x; i < N; i += blockDim.x) {
                int ixj = i ^ j;
                if (ixj > i) {
                    unsigned long long a = ssort[i];
                    unsigned long long c = ssort[ixj];
                    bool up = ((i & k) == 0);
                    if ((a > c) == up) { ssort[i] = c; ssort[ixj] = a; }
                }
            }
            __syncthreads();
        }
    }
    for (int i = threadIdx.x; i < TOPK; i += blockDim.x)
        d_sortbuf[b][i] = ssort[i];
}

// ---------------- per-keypoint soft-argmax / dispersity / bilinear rescore ----------------
__global__ void final_kernel(const float* __restrict__ s, float* __restrict__ out) {
    int g = blockIdx.x * blockDim.x + threadIdx.x;
    if (g >= BATCH * TOPK) return;
    int b = g / TOPK, k = g % TOPK;

    unsigned long long key = d_sortbuf[b][k];
    unsigned idx = (unsigned)key;
    int ky = (int)(idx >> 11);   // W = 2048
    int kx = (int)(idx & 2047u);
    const float* img = s + (size_t)b * HW;

    // 5x5 patch (keypoints are >= 2 px from every border -> fully in bounds)
    float p[25];
    float mx = -1e30f;
#pragma unroll
    for (int di = 0; di < 5; di++)
#pragma unroll
        for (int dj = 0; dj < 5; dj++) {
            float v = img[(ky + di - 2) * W + (kx + dj - 2)];
            p[di * 5 + dj] = v;
            mx = fmaxf(mx, v);
        }

    float e[25];
    float se = 0.f, sx = 0.f, sy = 0.f;
#pragma unroll
    for (int i = 0; i < 25; i++) {
        float dx = (float)(i % 5) - 2.0f;
        float dy = (float)(i / 5) - 2.0f;
        float ev = expf((p[i] - mx) * 10.0f);  // 1 / TEMPERATURE
        e[i] = ev;
        se += ev; sx += ev * dx; sy += ev * dy;
    }
    float xres = sx / se;
    float yres = sy / se;

    float dsum = 0.f;
#pragma unroll
    for (int i = 0; i < 25; i++) {
        float dx = ((float)(i % 5) - 2.0f - xres) * 0.5f;  // / RADIUS
        float dy = ((float)(i / 5) - 2.0f - yres) * 0.5f;
        dsum += e[i] * (dx * dx + dy * dy);
    }
    float disp = dsum / se;

    float kxy_x = ((float)kx + xres) / 2047.0f * 2.0f - 1.0f;
    float kxy_y = ((float)ky + yres) / 2047.0f * 2.0f - 1.0f;

    // bilinear resample (align_corners=True), matching reference clamp semantics
    float px = (kxy_x + 1.0f) * 0.5f * 2047.0f;
    float py = (kxy_y + 1.0f) * 0.5f * 2047.0f;
    int x0 = min(max((int)floorf(px), 0), W - 1);
    int y0 = min(max((int)floorf(py), 0), H - 1);
    int x1 = min(x0 + 1, W - 1);
    int y1 = min(y0 + 1, H - 1);
    float wx = px - (float)x0;
    float wy = py - (float)y0;
    float v00 = img[y0 * W + x0], v01 = img[y0 * W + x1];
    float v10 = img[y1 * W + x0], v11 = img[y1 * W + x1];
    float ks = v00 * (1.f - wx) * (1.f - wy) + v01 * wx * (1.f - wy)
             + v10 * (1.f - wx) * wy + v11 * wx * wy;

    // output layout: kxy (B,K,2) | kscore (B,K) | disp (B,K)
    out[(size_t)(b * TOPK + k) * 2 + 0] = kxy_x;
    out[(size_t)(b * TOPK + k) * 2 + 1] = kxy_y;
    out[(size_t)BATCH * TOPK * 2 + b * TOPK + k] = ks;
    out[(size_t)BATCH * TOPK * 3 + b * TOPK + k] = disp;
}

// ---------------- launch ----------------
extern "C" void kernel_launch(void* const* d_in, const int* in_sizes, int n_in,
                              void* d_out, int out_size) {
    const float* s = (const float*)d_in[0];
    float* out = (float*)d_out;

    // idempotent; needed for 128KB dynamic smem in sort_kernel
    cudaFuncSetAttribute(sort_kernel, cudaFuncAttributeMaxDynamicSharedMemorySize,
                         CAP * (int)sizeof(unsigned long long));

    init_kernel<<<1, 512>>>();
    nms_kernel<<<dim3(W / TX, H / TY, BATCH), 256>>>(s);
    for (int level = 3; level >= 0; level--) {
        hist_kernel<<<dim3(48, BATCH), 256>>>(level);
        select_kernel<<<1, BATCH>>>(level);
    }
    gather_kernel<<<dim3(48, BATCH), 256>>>();
    sort_kernel<<<BATCH, 1024, CAP * (int)sizeof(unsigned long long)>>>();
    final_kernel<<<(BATCH * TOPK + 255) / 256, 256>>>(s, out);
}

// round 4
// speedup vs baseline: 1.0533x; 1.0533x over previous
#include <cuda_runtime.h>
#include <stdint.h>

// Problem constants
#define BATCH 8
#define H 2048
#define W 2048
#define HW (H * W)
#define TOPK 8192
#define MAXP 400000      // per-batch peak capacity (expected ~167k)
#define NBINS 8192       // value histogram bins (mantissa bits [22:10] for v in [0.5,1))
#define CAPB 4096        // threshold-bin candidate capacity (expected ~250)

// ---------------- device scratch ----------------
__device__ unsigned long long d_peaks[BATCH][MAXP];   // key = (~float_bits)<<32 | idx
__device__ int                d_pcount[BATCH];
__device__ unsigned int       d_hist[BATCH][NBINS];
__device__ int                d_thrbin[BATCH];
__device__ int                d_cA[BATCH];
__device__ int                d_cB[BATCH];
__device__ unsigned long long d_bufA[BATCH][TOPK];
__device__ unsigned long long d_bufB[BATCH][CAPB];

// value -> bin, monotone: larger value => smaller bin
__device__ __forceinline__ unsigned value_bin(unsigned bits) {
    if (bits >= 0x3F800000u) return 0u;          // v >= 1.0 (shouldn't happen)
    if (bits <  0x3F000000u) return NBINS - 1u;  // v < 0.5: irrelevant, worst bin
    return (NBINS - 1u) - ((bits - 0x3F000000u) >> 10);
}

// ---------------- init ----------------
__global__ void init_kernel() {
    int g = blockIdx.x * blockDim.x + threadIdx.x;
    if (g < BATCH) {
        d_pcount[g] = 0;
        d_cA[g] = 0;
        d_cB[g] = 0;
        d_thrbin[g] = NBINS - 1;
    }
    for (int i = g; i < BATCH * NBINS; i += gridDim.x * blockDim.x)
        ((unsigned int*)d_hist)[i] = 0u;
}

// ---------------- NMS: 5x5 local max + fused value histogram ----------------
#define TX 128
#define TY 32
#define NTHR 512

__global__ __launch_bounds__(NTHR) void nms_kernel(const float* __restrict__ s) {
    __shared__ float tile[TY + 4][TX + 4];   // 36 x 132
    __shared__ float hmax[TY + 4][TX];       // 36 x 128

    int b  = blockIdx.z;
    int x0 = blockIdx.x * TX;
    int y0 = blockIdx.y * TY;
    const float* img = s + (size_t)b * HW;
    int tid = threadIdx.x;

    // Load tile + halo (clamped; clamped values only influence discarded border outputs)
    for (int i = tid; i < (TY + 4) * (TX + 4); i += NTHR) {
        int r = i / (TX + 4), c = i % (TX + 4);
        int gy = min(max(y0 + r - 2, 0), H - 1);
        int gx = min(max(x0 + c - 2, 0), W - 1);
        tile[r][c] = img[gy * W + gx];
    }
    __syncthreads();

    // Horizontal 5-max
    for (int i = tid; i < (TY + 4) * TX; i += NTHR) {
        int r = i / TX, c = i % TX;
        float m = tile[r][c];
        m = fmaxf(m, tile[r][c + 1]);
        m = fmaxf(m, tile[r][c + 2]);
        m = fmaxf(m, tile[r][c + 3]);
        m = fmaxf(m, tile[r][c + 4]);
        hmax[r][c] = m;
    }
    __syncthreads();

    // Vertical 5-max + peak test (warp-aggregated atomic append) + histogram
    int c  = tid & 127;
    int r0 = tid >> 7;  // 0..3, uniform within a warp
    for (int rr = r0; rr < TY; rr += 4) {
        float v = tile[rr + 2][c + 2];
        float m = hmax[rr][c];
        m = fmaxf(m, hmax[rr + 1][c]);
        m = fmaxf(m, hmax[rr + 2][c]);
        m = fmaxf(m, hmax[rr + 3][c]);
        m = fmaxf(m, hmax[rr + 4][c]);
        int gx = x0 + c, gy = y0 + rr;
        bool peak = (v >= m) && (gx >= 2) && (gx < W - 2) && (gy >= 2) && (gy < H - 2);

        unsigned ball = __ballot_sync(0xffffffffu, peak);
        if (ball) {
            int lane   = tid & 31;
            int leader = __ffs(ball) - 1;
            int base   = 0;
            if (lane == leader) base = atomicAdd(&d_pcount[b], __popc(ball));
            base = __shfl_sync(0xffffffffu, base, leader);
            if (peak) {
                int off = base + __popc(ball & ((1u << lane) - 1u));
                if (off < MAXP) {
                    unsigned bits = __float_as_uint(v);
                    unsigned idx  = (unsigned)(gy * W + gx);
                    d_peaks[b][off] = ((unsigned long long)(~bits) << 32) | idx;
                    atomicAdd(&d_hist[b][value_bin(bits)], 1u);
                }
            }
        }
    }
}

// ---------------- threshold bin via parallel scan (one block per batch) ----------------
__global__ void threshold_kernel() {
    __shared__ unsigned ssum[256];
    int b = blockIdx.x;
    int t = threadIdx.x;  // 256

    unsigned sum = 0;
#pragma unroll
    for (int i = 0; i < NBINS / 256; i++) sum += d_hist[b][t * (NBINS / 256) + i];
    ssum[t] = sum;
    __syncthreads();

    // inclusive Hillis-Steele scan
    for (int off = 1; off < 256; off <<= 1) {
        unsigned x = (t >= off) ? ssum[t - off] : 0u;
        __syncthreads();
        ssum[t] += x;
        __syncthreads();
    }
    unsigned incl = ssum[t];
    unsigned excl = incl - sum;

    if (excl < TOPK && incl >= TOPK) {
        unsigned cum = excl;
        for (int i = 0; i < NBINS / 256; i++) {
            unsigned cc = d_hist[b][t * (NBINS / 256) + i];
            if (cum + cc >= TOPK) { d_thrbin[b] = t * (NBINS / 256) + i; break; }
            cum += cc;
        }
    }
}

// ---------------- gather: split into A (above threshold bin) and B (threshold bin) ----------------
__global__ void gather_kernel() {
    int b = blockIdx.y;
    int n = min(d_pcount[b], MAXP);
    unsigned thr = (unsigned)d_thrbin[b];
    for (int i = blockIdx.x * blockDim.x + threadIdx.x; i < n; i += gridDim.x * blockDim.x) {
        unsigned long long key = d_peaks[b][i];
        unsigned bits = ~(unsigned)(key >> 32);
        unsigned bin = value_bin(bits);
        if (bin < thr) {
            int pos = atomicAdd(&d_cA[b], 1);
            if (pos < TOPK) d_bufA[b][pos] = key;
        } else if (bin == thr) {
            int pos = atomicAdd(&d_cB[b], 1);
            if (pos < CAPB) d_bufB[b][pos] = key;
        }
    }
}

// ---------------- bitonic sort (ascending 64-bit key = value desc, idx asc) ----------------
extern __shared__ unsigned long long ssort[];
__global__ void sort_kernel() {
    int b     = blockIdx.x;
    int which = blockIdx.y;  // 0 = A, 1 = B

    unsigned long long* buf = which ? &d_bufB[b][0] : &d_bufA[b][0];
    int cnt = which ? min(d_cB[b], CAPB) : min(d_cA[b], TOPK);
    int N;
    if (which) { N = 1024; while (N < cnt) N <<= 1; }  // <= CAPB
    else       { N = TOPK; }

    for (int i = threadIdx.x; i < N; i += blockDim.x)
        ssort[i] = (i < cnt) ? buf[i] : 0xFFFFFFFFFFFFFFFFull;
    __syncthreads();

    for (int k = 2; k <= N; k <<= 1) {
        for (int j = k >> 1; j > 0; j >>= 1) {
            for (int i = threadIdx.x; i < N; i += blockDim.x) {
                int ixj = i ^ j;
                if (ixj > i) {
                    unsigned long long a = ssort[i];
                    unsigned long long c = ssort[ixj];
                    bool up = ((i & k) == 0);
                    if ((a > c) == up) { ssort[i] = c; ssort[ixj] = a; }
                }
            }
            __syncthreads();
        }
    }
    for (int i = threadIdx.x; i < cnt; i += blockDim.x)
        buf[i] = ssort[i];
}

// ---------------- per-keypoint soft-argmax / dispersity / bilinear rescore ----------------
__global__ void final_kernel(const float* __restrict__ s, float* __restrict__ out) {
    int g = blockIdx.x * blockDim.x + threadIdx.x;
    if (g >= BATCH * TOPK) return;
    int b = g / TOPK, k = g % TOPK;

    int cA = min(d_cA[b], TOPK);
    unsigned long long key = (k < cA) ? d_bufA[b][k] : d_bufB[b][k - cA];
    unsigned idx = (unsigned)key;
    int ky = (int)(idx >> 11);   // W = 2048
    int kx = (int)(idx & 2047u);
    const float* img = s + (size_t)b * HW;

    // 5x5 patch (keypoints are >= 2 px from every border -> fully in bounds)
    float p[25];
    float mx = -1e30f;
#pragma unroll
    for (int di = 0; di < 5; di++)
#pragma unroll
        for (int dj = 0; dj < 5; dj++) {
            float v = img[(ky + di - 2) * W + (kx + dj - 2)];
            p[di * 5 + dj] = v;
            mx = fmaxf(mx, v);
        }

    float e[25];
    float se = 0.f, sx = 0.f, sy = 0.f;
#pragma unroll
    for (int i = 0; i < 25; i++) {
        float dx = (float)(i % 5) - 2.0f;
        float dy = (float)(i / 5) - 2.0f;
        float ev = expf((p[i] - mx) * 10.0f);  // 1 / TEMPERATURE
        e[i] = ev;
        se += ev; sx += ev * dx; sy += ev * dy;
    }
    float xres = sx / se;
    float yres = sy / se;

    float dsum = 0.f;
#pragma unroll
    for (int i = 0; i < 25; i++) {
        float dx = ((float)(i % 5) - 2.0f - xres) * 0.5f;  // / RADIUS
        float dy = ((float)(i / 5) - 2.0f - yres) * 0.5f;
        dsum += e[i] * (dx * dx + dy * dy);
    }
    float disp = dsum / se;

    float kxy_x = ((float)kx + xres) / 2047.0f * 2.0f - 1.0f;
    float kxy_y = ((float)ky + yres) / 2047.0f * 2.0f - 1.0f;

    // bilinear resample (align_corners=True), matching reference clamp semantics
    float px = (kxy_x + 1.0f) * 0.5f * 2047.0f;
    float py = (kxy_y + 1.0f) * 0.5f * 2047.0f;
    int x0 = min(max((int)floorf(px), 0), W - 1);
    int y0 = min(max((int)floorf(py), 0), H - 1);
    int x1 = min(x0 + 1, W - 1);
    int y1 = min(y0 + 1, H - 1);
    float wx = px - (float)x0;
    float wy = py - (float)y0;
    float v00 = img[y0 * W + x0], v01 = img[y0 * W + x1];
    float v10 = img[y1 * W + x0], v11 = img[y1 * W + x1];
    float ks = v00 * (1.f - wx) * (1.f - wy) + v01 * wx * (1.f - wy)
             + v10 * (1.f - wx) * wy + v11 * wx * wy;

    // output layout: kxy (B,K,2) | kscore (B,K) | disp (B,K)
    out[(size_t)(b * TOPK + k) * 2 + 0] = kxy_x;
    out[(size_t)(b * TOPK + k) * 2 + 1] = kxy_y;
    out[(size_t)BATCH * TOPK * 2 + b * TOPK + k] = ks;
    out[(size_t)BATCH * TOPK * 3 + b * TOPK + k] = disp;
}

// ---------------- launch ----------------
extern "C" void kernel_launch(void* const* d_in, const int* in_sizes, int n_in,
                              void* d_out, int out_size) {
    const float* s = (const float*)d_in[0];
    float* out = (float*)d_out;

    cudaFuncSetAttribute(sort_kernel, cudaFuncAttributeMaxDynamicSharedMemorySize,
                         TOPK * (int)sizeof(unsigned long long));

    init_kernel<<<256, 256>>>();
    nms_kernel<<<dim3(W / TX, H / TY, BATCH), NTHR>>>(s);
    threshold_kernel<<<BATCH, 256>>>();
    gather_kernel<<<dim3(48, BATCH), 256>>>();
    sort_kernel<<<dim3(BATCH, 2), 1024, TOPK * (int)sizeof(unsigned long long)>>>();
    final_kernel<<<(BATCH * TOPK + 255) / 256, 256>>>(s, out);
}